// round 10
// baseline (speedup 1.0000x reference)
#include <cuda_runtime.h>
#include <cuda_bf16.h>
#include <math.h>
#include <stdint.h>

// Problem constants
#define BB 2
#define LL 2048
#define D_MODEL 768
#define D_INNER 1536
#define DT_RANK 16
#define D_STATE 16
#define D_CONV 4
#define MROWS (BB*LL)          // 4096
#define N_IN (2*D_INNER)       // 3072
#define N_DBL (DT_RANK + 2*D_STATE) // 48

// Scratch (static __device__ — no allocation in kernel_launch)
__device__ float g_xz[(size_t)MROWS * N_IN];       // [4096,3072]
__device__ float g_xconv[(size_t)MROWS * D_INNER]; // [4096,1536]
__device__ float g_xdbl[(size_t)MROWS * N_DBL];    // [4096,48]
__device__ float g_dt[(size_t)MROWS * D_INNER];    // [4096,1536]
__device__ float g_yg[(size_t)MROWS * D_INNER];    // [4096,1536]

// ---------------------------------------------------------------------------
// TF32 tensor-core GEMM with 4-stage cp.async pipeline. (unchanged from R5)
// ---------------------------------------------------------------------------
__device__ __forceinline__ float to_tf32(float x) {
    float y;
    asm("cvt.rna.tf32.f32 %0, %1;" : "=f"(y) : "f"(x));
    return y;
}

#define MMA_TF32(d, a, b) \
    asm volatile("mma.sync.aligned.m16n8k8.row.col.f32.tf32.tf32.f32 " \
                 "{%0,%1,%2,%3},{%4,%5,%6,%7},{%8,%9},{%0,%1,%2,%3};" \
                 : "+f"((d)[0]), "+f"((d)[1]), "+f"((d)[2]), "+f"((d)[3]) \
                 : "r"((a)[0]), "r"((a)[1]), "r"((a)[2]), "r"((a)[3]), \
                   "r"((b)[0]), "r"((b)[1]))

__device__ __forceinline__ uint32_t smem_u32(const void* p) {
    return (uint32_t)__cvta_generic_to_shared(p);
}
#define CP_ASYNC16(dst, src) \
    asm volatile("cp.async.cg.shared.global [%0], [%1], 16;" :: "r"(dst), "l"(src))
#define CP_COMMIT() asm volatile("cp.async.commit_group;")
#define CP_WAIT2()  asm volatile("cp.async.wait_group 2;")
#define CP_WAIT0()  asm volatile("cp.async.wait_group 0;")

#define STAGES 4
__global__ __launch_bounds__(256) void tf32_gemm(
    const float* __restrict__ A, const float* __restrict__ B,
    float* __restrict__ C, int M, int N, int K)
{
    __shared__ float As[STAGES][128][20];
    __shared__ float Bs[STAGES][16][132];

    const int tid  = threadIdx.x;
    const int lane = tid & 31;
    const int warp = tid >> 5;
    const int warp_m = warp >> 1;   // 0..3  (32 rows)
    const int warp_n = warp & 1;    // 0..1  (64 cols)
    const int bx = blockIdx.x, by = blockIdx.y;
    const int KT = K >> 4;

    const int ea0 = tid, ea1 = tid + 256;
    const int ar0 = ea0 >> 2, ac0 = (ea0 & 3) * 4;
    const int ar1 = ea1 >> 2, ac1 = (ea1 & 3) * 4;
    const int br0 = ea0 >> 5, bc0 = (ea0 & 31) * 4;
    const int br1 = ea1 >> 5, bc1 = (ea1 & 31) * 4;

    const float* Aab = A + (size_t)(by * 128) * K;
    const float* Bbb = B + bx * 128;

#define LOAD_STAGE(s, k0) do { \
        CP_ASYNC16(smem_u32(&As[s][ar0][ac0]), Aab + (size_t)ar0 * K + (k0) + ac0); \
        CP_ASYNC16(smem_u32(&As[s][ar1][ac1]), Aab + (size_t)ar1 * K + (k0) + ac1); \
        CP_ASYNC16(smem_u32(&Bs[s][br0][bc0]), Bbb + (size_t)((k0) + br0) * N + bc0); \
        CP_ASYNC16(smem_u32(&Bs[s][br1][bc1]), Bbb + (size_t)((k0) + br1) * N + bc1); \
    } while (0)

    LOAD_STAGE(0, 0);  CP_COMMIT();
    LOAD_STAGE(1, 16); CP_COMMIT();
    LOAD_STAGE(2, 32); CP_COMMIT();

    float acc[2][8][4];
    #pragma unroll
    for (int mt = 0; mt < 2; mt++)
        #pragma unroll
        for (int nt = 0; nt < 8; nt++)
            #pragma unroll
            for (int i = 0; i < 4; i++) acc[mt][nt][i] = 0.f;

    for (int kt = 0; kt < KT; kt++) {
        if (kt + 3 < KT) { CP_WAIT2(); } else { CP_WAIT0(); }
        __syncthreads();
        {
            int kn = kt + 3;
            if (kn < KT) {
                int s = kn & (STAGES - 1);
                LOAD_STAGE(s, kn * 16);
            }
            CP_COMMIT();
        }

        const int buf = kt & (STAGES - 1);
        #pragma unroll
        for (int ks = 0; ks < 16; ks += 8) {
            uint32_t af[2][4];
            #pragma unroll
            for (int mt = 0; mt < 2; mt++) {
                int row = warp_m * 32 + mt * 16 + (lane >> 2);
                int col = ks + (lane & 3);
                af[mt][0] = __float_as_uint(to_tf32(As[buf][row    ][col    ]));
                af[mt][1] = __float_as_uint(to_tf32(As[buf][row + 8][col    ]));
                af[mt][2] = __float_as_uint(to_tf32(As[buf][row    ][col + 4]));
                af[mt][3] = __float_as_uint(to_tf32(As[buf][row + 8][col + 4]));
            }
            uint32_t bf[8][2];
            #pragma unroll
            for (int nt = 0; nt < 8; nt++) {
                int col = warp_n * 64 + nt * 8 + (lane >> 2);
                int row = ks + (lane & 3);
                bf[nt][0] = __float_as_uint(to_tf32(Bs[buf][row    ][col]));
                bf[nt][1] = __float_as_uint(to_tf32(Bs[buf][row + 4][col]));
            }
            #pragma unroll
            for (int mt = 0; mt < 2; mt++)
                #pragma unroll
                for (int nt = 0; nt < 8; nt++)
                    MMA_TF32(acc[mt][nt], af[mt], bf[nt]);
        }
    }
#undef LOAD_STAGE

    #pragma unroll
    for (int mt = 0; mt < 2; mt++) {
        #pragma unroll
        for (int nt = 0; nt < 8; nt++) {
            int row = by * 128 + warp_m * 32 + mt * 16 + (lane >> 2);
            int col = bx * 128 + warp_n * 64 + nt * 8 + 2 * (lane & 3);
            float2 v0 = make_float2(acc[mt][nt][0], acc[mt][nt][1]);
            float2 v1 = make_float2(acc[mt][nt][2], acc[mt][nt][3]);
            *(float2*)(C + (size_t)row * N + col)       = v0;
            *(float2*)(C + (size_t)(row + 8) * N + col) = v1;
        }
    }
}

// ---------------------------------------------------------------------------
// Causal depthwise conv1d (width 4) + silu.
// ---------------------------------------------------------------------------
__global__ void conv_silu_kernel(const float* __restrict__ conv_w,
                                 const float* __restrict__ conv_b)
{
    int idx = blockIdx.x * blockDim.x + threadIdx.x;   // over 4096*1536
    if (idx >= MROWS * D_INNER) return;
    int d = idx % D_INNER;
    int r = idx / D_INNER;
    int l = r % LL;

    float w0 = conv_w[d*4+0], w1 = conv_w[d*4+1], w2 = conv_w[d*4+2], w3 = conv_w[d*4+3];
    const float* base = g_xz + (size_t)r * N_IN + d;

    float acc = conv_b[d] + w3 * base[0];
    if (l >= 1) acc += w2 * base[-(size_t)N_IN];
    if (l >= 2) acc += w1 * base[-2*(size_t)N_IN];
    if (l >= 3) acc += w0 * base[-3*(size_t)N_IN];
    g_xconv[idx] = acc / (1.f + __expf(-acc));   // silu
}

// ---------------------------------------------------------------------------
// x_dbl = x_conv @ W_x  ([4096,1536] x [1536,48]).
// ---------------------------------------------------------------------------
__global__ __launch_bounds__(256) void xdbl_kernel(const float* __restrict__ Wx)
{
    const int tx = threadIdx.x & 15;
    const int ty = threadIdx.x >> 4;
    const int r0 = blockIdx.x * 64;

    float acc[4][3] = {};
    #pragma unroll 4
    for (int k = 0; k < D_INNER; k++) {
        float w0 = Wx[k * N_DBL + tx];
        float w1 = Wx[k * N_DBL + tx + 16];
        float w2 = Wx[k * N_DBL + tx + 32];
        #pragma unroll
        for (int rr = 0; rr < 4; rr++) {
            float xv = g_xconv[(size_t)(r0 + ty + rr * 16) * D_INNER + k];
            acc[rr][0] += xv * w0;
            acc[rr][1] += xv * w1;
            acc[rr][2] += xv * w2;
        }
    }
    #pragma unroll
    for (int rr = 0; rr < 4; rr++) {
        int r = r0 + ty + rr * 16;
        g_xdbl[(size_t)r * N_DBL + tx]      = acc[rr][0];
        g_xdbl[(size_t)r * N_DBL + tx + 16] = acc[rr][1];
        g_xdbl[(size_t)r * N_DBL + tx + 32] = acc[rr][2];
    }
}

// ---------------------------------------------------------------------------
// dt = softplus(dt_low @ W_dt + b_dt)    K=16, thread per output.
// ---------------------------------------------------------------------------
__global__ void dt_kernel(const float* __restrict__ Wdt, const float* __restrict__ bdt)
{
    int idx = blockIdx.x * blockDim.x + threadIdx.x;
    if (idx >= MROWS * D_INNER) return;
    int d = idx % D_INNER;
    int r = idx / D_INNER;
    float acc = bdt[d];
    #pragma unroll
    for (int k = 0; k < DT_RANK; k++)
        acc += g_xdbl[(size_t)r * N_DBL + k] * Wdt[(size_t)k * D_INNER + d];
    g_dt[idx] = (acc > 20.f) ? acc : log1pf(__expf(acc));
}

// ---------------------------------------------------------------------------
// Selective scan with DEEP software pipeline.
// 16 lanes per channel (one per state n), 4 channels per 64-thread block.
// Inputs are consumed in blocks of UF=8 timesteps from register buffers;
// the next 8-step block's loads (5 streams x 8) are issued before computing
// the current block, so per-step exposed memory latency ~ max(0, lat - 8*body).
// ---------------------------------------------------------------------------
#define UF 8

__global__ __launch_bounds__(64) void scan_kernel(
    const float* __restrict__ A_log, const float* __restrict__ Dvec)
{
    const int n  = threadIdx.x & 15;
    const int ch = blockIdx.x * 4 + (threadIdx.x >> 4);  // 0..3071
    const int b  = ch / D_INNER;
    const int d  = ch % D_INNER;

    const float A  = -__expf(A_log[d * D_STATE + n]);
    const float Dd = Dvec[d];

    const float* xc  = g_xconv + (size_t)b * LL * D_INNER + d;
    const float* dtp = g_dt    + (size_t)b * LL * D_INNER + d;
    const float* bc  = g_xdbl  + (size_t)b * LL * N_DBL;
    const float* zp  = g_xz    + (size_t)b * LL * N_IN + D_INNER + d;
    float*       yp  = g_yg    + (size_t)b * LL * D_INNER + d;

    float h = 0.f;

    float uA[UF], dA_[UF], BA[UF], CA[UF], zA[UF];
    float uB[UF], dB_[UF], BBf[UF], CB[UF], zB[UF];

    auto loadblk = [&](int t0, float* U, float* DT, float* Bv, float* Cv, float* Z) {
        #pragma unroll
        for (int i = 0; i < UF; i++) {
            size_t t = (size_t)(t0 + i);
            U[i]  = __ldg(xc  + t * D_INNER);
            DT[i] = __ldg(dtp + t * D_INNER);
            Bv[i] = __ldg(bc  + t * N_DBL + DT_RANK + n);
            Cv[i] = __ldg(bc  + t * N_DBL + DT_RANK + D_STATE + n);
            Z[i]  = __ldg(zp  + t * N_IN);
        }
    };
    auto compute = [&](int t0, const float* U, const float* DT,
                       const float* Bv, const float* Cv, const float* Z) {
        #pragma unroll
        for (int i = 0; i < UF; i++) {
            float dA = __expf(A * DT[i]);
            h = h * dA + (DT[i] * U[i]) * Bv[i];

            float p = Cv[i] * h;
            p += __shfl_xor_sync(0xffffffffu, p, 8);
            p += __shfl_xor_sync(0xffffffffu, p, 4);
            p += __shfl_xor_sync(0xffffffffu, p, 2);
            p += __shfl_xor_sync(0xffffffffu, p, 1);

            if (n == 0) {
                float zv = Z[i];
                float zs = zv / (1.f + __expf(-zv));
                yp[(size_t)(t0 + i) * D_INNER] = (p + U[i] * Dd) * zs;
            }
        }
    };

    // prologue: block 0 into A-buffers
    loadblk(0, uA, dA_, BA, CA, zA);

    // 2048 / (2*UF) = 128 iterations, ping-pong A/B buffers
    for (int t0 = 0; t0 < LL; t0 += 2 * UF) {
        loadblk(t0 + UF, uB, dB_, BBf, CB, zB);
        compute(t0, uA, dA_, BA, CA, zA);
        if (t0 + 2 * UF < LL)
            loadblk(t0 + 2 * UF, uA, dA_, BA, CA, zA);
        compute(t0 + UF, uB, dB_, BBf, CB, zB);
    }
}

// ---------------------------------------------------------------------------
extern "C" void kernel_launch(void* const* d_in, const int* in_sizes, int n_in,
                              void* d_out, int out_size)
{
    const float* x      = (const float*)d_in[0];
    const float* W_in   = (const float*)d_in[1];
    const float* conv_w = (const float*)d_in[2];
    const float* conv_b = (const float*)d_in[3];
    const float* W_x    = (const float*)d_in[4];
    const float* W_dt   = (const float*)d_in[5];
    const float* b_dt   = (const float*)d_in[6];
    const float* A_log  = (const float*)d_in[7];
    const float* Dvec   = (const float*)d_in[8];
    const float* W_out  = (const float*)d_in[9];
    float* out = (float*)d_out;

    float *xz_p, *yg_p;
    cudaGetSymbolAddress((void**)&xz_p, g_xz);
    cudaGetSymbolAddress((void**)&yg_p, g_yg);

    // 1) xz = x @ W_in   [4096,768] x [768,3072]
    {
        dim3 grid(N_IN / 128, MROWS / 128);
        tf32_gemm<<<grid, 256>>>(x, W_in, xz_p, MROWS, N_IN, D_MODEL);
    }
    // 2) causal conv + silu
    {
        int total = MROWS * D_INNER;
        conv_silu_kernel<<<(total + 255) / 256, 256>>>(conv_w, conv_b);
    }
    // 3) x_dbl = x_conv @ W_x
    xdbl_kernel<<<MROWS / 64, 256>>>(W_x);
    // 4) dt = softplus(dt_low @ W_dt + b_dt)
    {
        int total = MROWS * D_INNER;
        dt_kernel<<<(total + 255) / 256, 256>>>(W_dt, b_dt);
    }
    // 5) selective scan + gate (deep-pipelined)
    scan_kernel<<<(BB * D_INNER) / 4, 64>>>(A_log, Dvec);
    // 6) out = y_gated @ W_out   [4096,1536] x [1536,768]
    {
        dim3 grid(D_MODEL / 128, MROWS / 128);
        tf32_gemm<<<grid, 256>>>(yg_p, W_out, out, MROWS, D_MODEL, D_INNER);
    }
}

// round 11
// speedup vs baseline: 1.0294x; 1.0294x over previous
#include <cuda_runtime.h>
#include <cuda_bf16.h>
#include <math.h>
#include <stdint.h>

// Problem constants
#define BB 2
#define LL 2048
#define D_MODEL 768
#define D_INNER 1536
#define DT_RANK 16
#define D_STATE 16
#define D_CONV 4
#define MROWS (BB*LL)          // 4096
#define N_IN (2*D_INNER)       // 3072
#define N_DBL (DT_RANK + 2*D_STATE) // 48

// Scratch (static __device__ — no allocation in kernel_launch)
__device__ float g_xz[(size_t)MROWS * N_IN];       // [4096,3072]
__device__ float g_xconv[(size_t)MROWS * D_INNER]; // [4096,1536]
__device__ float g_xdbl[(size_t)MROWS * N_DBL];    // [4096,48]
__device__ float g_dt[(size_t)MROWS * D_INNER];    // [4096,1536]
__device__ float g_yg[(size_t)MROWS * D_INNER];    // [4096,1536]

// ---------------------------------------------------------------------------
// TF32 tensor-core GEMM, 4-stage cp.async pipeline.
// CTA tile 128x128x16, 4 warps (2m x 2n), warp tile 64x64, mma.m16n8k8.tf32.
// Requires M%128==0, N%128==0, K%16==0.
// ---------------------------------------------------------------------------
__device__ __forceinline__ float to_tf32(float x) {
    float y;
    asm("cvt.rna.tf32.f32 %0, %1;" : "=f"(y) : "f"(x));
    return y;
}

#define MMA_TF32(d, a, b) \
    asm volatile("mma.sync.aligned.m16n8k8.row.col.f32.tf32.tf32.f32 " \
                 "{%0,%1,%2,%3},{%4,%5,%6,%7},{%8,%9},{%0,%1,%2,%3};" \
                 : "+f"((d)[0]), "+f"((d)[1]), "+f"((d)[2]), "+f"((d)[3]) \
                 : "r"((a)[0]), "r"((a)[1]), "r"((a)[2]), "r"((a)[3]), \
                   "r"((b)[0]), "r"((b)[1]))

__device__ __forceinline__ uint32_t smem_u32(const void* p) {
    return (uint32_t)__cvta_generic_to_shared(p);
}
#define CP_ASYNC16(dst, src) \
    asm volatile("cp.async.cg.shared.global [%0], [%1], 16;" :: "r"(dst), "l"(src))
#define CP_COMMIT() asm volatile("cp.async.commit_group;")
#define CP_WAIT2()  asm volatile("cp.async.wait_group 2;")
#define CP_WAIT0()  asm volatile("cp.async.wait_group 0;")

#define STAGES 4
// As rows padded to 20 floats: frag banks (20*r + c) mod 32 distinct.
// Bs rows padded to 136 floats: frag banks (8*(lane&3) + (lane>>2)) distinct.
__global__ __launch_bounds__(128) void tf32_gemm(
    const float* __restrict__ A, const float* __restrict__ B,
    float* __restrict__ C, int M, int N, int K)
{
    __shared__ float As[STAGES][128][20];
    __shared__ float Bs[STAGES][16][136];

    const int tid  = threadIdx.x;
    const int lane = tid & 31;
    const int warp = tid >> 5;          // 0..3
    const int warp_m = warp >> 1;       // 0..1  (64 rows)
    const int warp_n = warp & 1;        // 0..1  (64 cols)
    const int bx = blockIdx.x, by = blockIdx.y;
    const int KT = K >> 4;

    const float* Aab = A + (size_t)(by * 128) * K;
    const float* Bbb = B + bx * 128;

    // per-thread cp.async chunks: A tile 128x16 = 512 float4, B tile 16x128 = 512 float4
    // 4 chunks of each per thread (128 threads).
#define LOAD_STAGE(s, k0) do { \
        _Pragma("unroll") \
        for (int i = 0; i < 4; i++) { \
            int e = tid + i * 128; \
            int ar = e >> 2, ac = (e & 3) * 4; \
            CP_ASYNC16(smem_u32(&As[s][ar][ac]), Aab + (size_t)ar * K + (k0) + ac); \
            int br = e >> 5, bc = (e & 31) * 4; \
            CP_ASYNC16(smem_u32(&Bs[s][br][bc]), Bbb + (size_t)((k0) + br) * N + bc); \
        } \
    } while (0)

    LOAD_STAGE(0, 0);  CP_COMMIT();
    LOAD_STAGE(1, 16); CP_COMMIT();
    LOAD_STAGE(2, 32); CP_COMMIT();

    float acc[4][8][4];
    #pragma unroll
    for (int mt = 0; mt < 4; mt++)
        #pragma unroll
        for (int nt = 0; nt < 8; nt++)
            #pragma unroll
            for (int i = 0; i < 4; i++) acc[mt][nt][i] = 0.f;

    for (int kt = 0; kt < KT; kt++) {
        if (kt + 3 < KT) { CP_WAIT2(); } else { CP_WAIT0(); }
        __syncthreads();
        {
            int kn = kt + 3;
            if (kn < KT) {
                int s = kn & (STAGES - 1);
                LOAD_STAGE(s, kn * 16);
            }
            CP_COMMIT();
        }

        const int buf = kt & (STAGES - 1);
        #pragma unroll
        for (int ks = 0; ks < 16; ks += 8) {
            uint32_t af[4][4];
            #pragma unroll
            for (int mt = 0; mt < 4; mt++) {
                int row = warp_m * 64 + mt * 16 + (lane >> 2);
                int col = ks + (lane & 3);
                af[mt][0] = __float_as_uint(to_tf32(As[buf][row    ][col    ]));
                af[mt][1] = __float_as_uint(to_tf32(As[buf][row + 8][col    ]));
                af[mt][2] = __float_as_uint(to_tf32(As[buf][row    ][col + 4]));
                af[mt][3] = __float_as_uint(to_tf32(As[buf][row + 8][col + 4]));
            }
            uint32_t bf[8][2];
            #pragma unroll
            for (int nt = 0; nt < 8; nt++) {
                int col = warp_n * 64 + nt * 8 + (lane >> 2);
                int row = ks + (lane & 3);
                bf[nt][0] = __float_as_uint(to_tf32(Bs[buf][row    ][col]));
                bf[nt][1] = __float_as_uint(to_tf32(Bs[buf][row + 4][col]));
            }
            #pragma unroll
            for (int mt = 0; mt < 4; mt++)
                #pragma unroll
                for (int nt = 0; nt < 8; nt++)
                    MMA_TF32(acc[mt][nt], af[mt], bf[nt]);
        }
    }
#undef LOAD_STAGE

    // epilogue: write C (fp32)
    #pragma unroll
    for (int mt = 0; mt < 4; mt++) {
        #pragma unroll
        for (int nt = 0; nt < 8; nt++) {
            int row = by * 128 + warp_m * 64 + mt * 16 + (lane >> 2);
            int col = bx * 128 + warp_n * 64 + nt * 8 + 2 * (lane & 3);
            float2 v0 = make_float2(acc[mt][nt][0], acc[mt][nt][1]);
            float2 v1 = make_float2(acc[mt][nt][2], acc[mt][nt][3]);
            *(float2*)(C + (size_t)row * N + col)       = v0;
            *(float2*)(C + (size_t)(row + 8) * N + col) = v1;
        }
    }
}

// ---------------------------------------------------------------------------
// Causal depthwise conv1d (width 4) + silu.
// ---------------------------------------------------------------------------
__global__ void conv_silu_kernel(const float* __restrict__ conv_w,
                                 const float* __restrict__ conv_b)
{
    int idx = blockIdx.x * blockDim.x + threadIdx.x;   // over 4096*1536
    if (idx >= MROWS * D_INNER) return;
    int d = idx % D_INNER;
    int r = idx / D_INNER;
    int l = r % LL;

    float w0 = conv_w[d*4+0], w1 = conv_w[d*4+1], w2 = conv_w[d*4+2], w3 = conv_w[d*4+3];
    const float* base = g_xz + (size_t)r * N_IN + d;

    float acc = conv_b[d] + w3 * base[0];
    if (l >= 1) acc += w2 * base[-(size_t)N_IN];
    if (l >= 2) acc += w1 * base[-2*(size_t)N_IN];
    if (l >= 3) acc += w0 * base[-3*(size_t)N_IN];
    g_xconv[idx] = acc / (1.f + __expf(-acc));   // silu
}

// ---------------------------------------------------------------------------
// x_dbl = x_conv @ W_x  ([4096,1536] x [1536,48]).
// ---------------------------------------------------------------------------
__global__ __launch_bounds__(256) void xdbl_kernel(const float* __restrict__ Wx)
{
    const int tx = threadIdx.x & 15;
    const int ty = threadIdx.x >> 4;
    const int r0 = blockIdx.x * 64;

    float acc[4][3] = {};
    #pragma unroll 4
    for (int k = 0; k < D_INNER; k++) {
        float w0 = Wx[k * N_DBL + tx];
        float w1 = Wx[k * N_DBL + tx + 16];
        float w2 = Wx[k * N_DBL + tx + 32];
        #pragma unroll
        for (int rr = 0; rr < 4; rr++) {
            float xv = g_xconv[(size_t)(r0 + ty + rr * 16) * D_INNER + k];
            acc[rr][0] += xv * w0;
            acc[rr][1] += xv * w1;
            acc[rr][2] += xv * w2;
        }
    }
    #pragma unroll
    for (int rr = 0; rr < 4; rr++) {
        int r = r0 + ty + rr * 16;
        g_xdbl[(size_t)r * N_DBL + tx]      = acc[rr][0];
        g_xdbl[(size_t)r * N_DBL + tx + 16] = acc[rr][1];
        g_xdbl[(size_t)r * N_DBL + tx + 32] = acc[rr][2];
    }
}

// ---------------------------------------------------------------------------
// dt = softplus(dt_low @ W_dt + b_dt)    K=16, thread per output.
// ---------------------------------------------------------------------------
__global__ void dt_kernel(const float* __restrict__ Wdt, const float* __restrict__ bdt)
{
    int idx = blockIdx.x * blockDim.x + threadIdx.x;
    if (idx >= MROWS * D_INNER) return;
    int d = idx % D_INNER;
    int r = idx / D_INNER;
    float acc = bdt[d];
    #pragma unroll
    for (int k = 0; k < DT_RANK; k++)
        acc += g_xdbl[(size_t)r * N_DBL + k] * Wdt[(size_t)k * D_INNER + d];
    g_dt[idx] = (acc > 20.f) ? acc : log1pf(__expf(acc));
}

// ---------------------------------------------------------------------------
// Selective scan with deep software pipeline (unchanged from R10).
// ---------------------------------------------------------------------------
#define UF 8

__global__ __launch_bounds__(64) void scan_kernel(
    const float* __restrict__ A_log, const float* __restrict__ Dvec)
{
    const int n  = threadIdx.x & 15;
    const int ch = blockIdx.x * 4 + (threadIdx.x >> 4);  // 0..3071
    const int b  = ch / D_INNER;
    const int d  = ch % D_INNER;

    const float A  = -__expf(A_log[d * D_STATE + n]);
    const float Dd = Dvec[d];

    const float* xc  = g_xconv + (size_t)b * LL * D_INNER + d;
    const float* dtp = g_dt    + (size_t)b * LL * D_INNER + d;
    const float* bc  = g_xdbl  + (size_t)b * LL * N_DBL;
    const float* zp  = g_xz    + (size_t)b * LL * N_IN + D_INNER + d;
    float*       yp  = g_yg    + (size_t)b * LL * D_INNER + d;

    float h = 0.f;

    float uA[UF], dA_[UF], BA[UF], CA[UF], zA[UF];
    float uB[UF], dB_[UF], BBf[UF], CB[UF], zB[UF];

    auto loadblk = [&](int t0, float* U, float* DT, float* Bv, float* Cv, float* Z) {
        #pragma unroll
        for (int i = 0; i < UF; i++) {
            size_t t = (size_t)(t0 + i);
            U[i]  = __ldg(xc  + t * D_INNER);
            DT[i] = __ldg(dtp + t * D_INNER);
            Bv[i] = __ldg(bc  + t * N_DBL + DT_RANK + n);
            Cv[i] = __ldg(bc  + t * N_DBL + DT_RANK + D_STATE + n);
            Z[i]  = __ldg(zp  + t * N_IN);
        }
    };
    auto compute = [&](int t0, const float* U, const float* DT,
                       const float* Bv, const float* Cv, const float* Z) {
        #pragma unroll
        for (int i = 0; i < UF; i++) {
            float dA = __expf(A * DT[i]);
            h = h * dA + (DT[i] * U[i]) * Bv[i];

            float p = Cv[i] * h;
            p += __shfl_xor_sync(0xffffffffu, p, 8);
            p += __shfl_xor_sync(0xffffffffu, p, 4);
            p += __shfl_xor_sync(0xffffffffu, p, 2);
            p += __shfl_xor_sync(0xffffffffu, p, 1);

            if (n == 0) {
                float zv = Z[i];
                float zs = zv / (1.f + __expf(-zv));
                yp[(size_t)(t0 + i) * D_INNER] = (p + U[i] * Dd) * zs;
            }
        }
    };

    loadblk(0, uA, dA_, BA, CA, zA);

    for (int t0 = 0; t0 < LL; t0 += 2 * UF) {
        loadblk(t0 + UF, uB, dB_, BBf, CB, zB);
        compute(t0, uA, dA_, BA, CA, zA);
        if (t0 + 2 * UF < LL)
            loadblk(t0 + 2 * UF, uA, dA_, BA, CA, zA);
        compute(t0 + UF, uB, dB_, BBf, CB, zB);
    }
}

// ---------------------------------------------------------------------------
extern "C" void kernel_launch(void* const* d_in, const int* in_sizes, int n_in,
                              void* d_out, int out_size)
{
    const float* x      = (const float*)d_in[0];
    const float* W_in   = (const float*)d_in[1];
    const float* conv_w = (const float*)d_in[2];
    const float* conv_b = (const float*)d_in[3];
    const float* W_x    = (const float*)d_in[4];
    const float* W_dt   = (const float*)d_in[5];
    const float* b_dt   = (const float*)d_in[6];
    const float* A_log  = (const float*)d_in[7];
    const float* Dvec   = (const float*)d_in[8];
    const float* W_out  = (const float*)d_in[9];
    float* out = (float*)d_out;

    float *xz_p, *yg_p;
    cudaGetSymbolAddress((void**)&xz_p, g_xz);
    cudaGetSymbolAddress((void**)&yg_p, g_yg);

    // 1) xz = x @ W_in   [4096,768] x [768,3072]
    {
        dim3 grid(N_IN / 128, MROWS / 128);
        tf32_gemm<<<grid, 128>>>(x, W_in, xz_p, MROWS, N_IN, D_MODEL);
    }
    // 2) causal conv + silu
    {
        int total = MROWS * D_INNER;
        conv_silu_kernel<<<(total + 255) / 256, 256>>>(conv_w, conv_b);
    }
    // 3) x_dbl = x_conv @ W_x
    xdbl_kernel<<<MROWS / 64, 256>>>(W_x);
    // 4) dt = softplus(dt_low @ W_dt + b_dt)
    {
        int total = MROWS * D_INNER;
        dt_kernel<<<(total + 255) / 256, 256>>>(W_dt, b_dt);
    }
    // 5) selective scan + gate (deep-pipelined)
    scan_kernel<<<(BB * D_INNER) / 4, 64>>>(A_log, Dvec);
    // 6) out = y_gated @ W_out   [4096,1536] x [1536,768]
    {
        dim3 grid(D_MODEL / 128, MROWS / 128);
        tf32_gemm<<<grid, 128>>>(yg_p, W_out, out, MROWS, D_MODEL, D_INNER);
    }
}